// round 5
// baseline (speedup 1.0000x reference)
#include <cuda_runtime.h>
#include <math.h>

#define NVOX   32768
#define BATCH  4
#define NROWS  (BATCH*NVOX)
#define NCLASS 10
#define TOPK   500

// ---------------- static device scratch (no allocations allowed) ----------------
__device__ float g_W1f[6*128*128];   // BN-folded first-layer weights
__device__ float g_b1f[6*128];       // BN-folded bias
__device__ float g_W2[6*128*10];     // padded second-layer weights [head][n][j]
__device__ float g_b2[6*10];
__device__ float g_hm[NROWS*10];     // sigmoid heatmap
__device__ float g_outs[NROWS*10];   // center(2) center_z(1) dim(3) rot(2) vel(2)
__device__ unsigned long long g_cand[BATCH*NCLASS*8*500];
__device__ float g_pc_score[BATCH*NCLASS*500];
__device__ int   g_pc_vox[BATCH*NCLASS*500];
__device__ float g_top_score[BATCH*500];
__device__ int   g_top_cls[BATCH*500];
__device__ int   g_top_vox[BATCH*500];

__constant__ int c_oc[6] = {10,2,1,3,2,2};

struct Ptrs {
    const float* W1; const float* b1;
    const float* ga; const float* be; const float* mu; const float* va;
    const float* W2[6]; const float* b2[6];
};

// ---------------- BN fold + weight packing ----------------
__global__ void fold_kernel(Ptrs P) {
    int idx = blockIdx.x * blockDim.x + threadIdx.x;
    if (idx < 6*128*128) {
        int hd = idx >> 14;
        int rem = idx & 16383;
        int c = rem >> 7;
        int d = rem & 127;
        float inv = P.ga[hd*128+d] / sqrtf(P.va[hd*128+d] + 1e-5f);
        g_W1f[idx] = P.W1[idx] * inv;
        if (c == 0)
            g_b1f[hd*128+d] = (P.b1[hd*128+d] - P.mu[hd*128+d]) * inv + P.be[hd*128+d];
    }
    if (idx < 6*1280) {
        int hd = idx / 1280, t = idx % 1280, n = t / 10, j = t % 10;
        int oc = c_oc[hd];
        g_W2[idx] = (j < oc) ? P.W2[hd][n*oc + j] : 0.f;
    }
    if (idx < 60) {
        int hd = idx / 10, j = idx % 10;
        g_b2[idx] = (j < c_oc[hd]) ? P.b2[hd][j] : 0.f;
    }
}

// ---------------- packed f32x2 helpers ----------------
__device__ __forceinline__ void ffma2(unsigned long long &d, unsigned long long a, unsigned long long b) {
    asm("fma.rn.f32x2 %0, %1, %2, %0;" : "+l"(d) : "l"(a), "l"(b));
}
__device__ __forceinline__ unsigned long long pack2(float x) {
    unsigned long long r; unsigned u = __float_as_uint(x);
    asm("mov.b64 %0, {%1, %1};" : "=l"(r) : "r"(u));
    return r;
}
__device__ __forceinline__ float2 unpack2(unsigned long long v) {
    unsigned lo, hi;
    asm("mov.b64 {%0, %1}, %2;" : "=r"(lo), "=r"(hi) : "l"(v));
    return make_float2(__uint_as_float(lo), __uint_as_float(hi));
}

// ---------------- fused head GEMM: h = relu(feats@W1f + b1f); out = h@W2 + b2 ----------------
// grid (1024, 6): x = 128-row tile, y = head. 256 threads, 8x8 microtile, BK=8 double-buffered.
__global__ void __launch_bounds__(256, 2) head_gemm(const float* __restrict__ feats) {
    __shared__ __align__(16) float As[2][8][128];
    __shared__ __align__(16) float Bs[2][8][128];
    __shared__ __align__(16) float Hs[128][33];
    __shared__ __align__(16) float W2t[10][128];
    __shared__ float b2s[10];

    const int tid = threadIdx.x;
    const int hd  = blockIdx.y;
    const int row0 = blockIdx.x * 128;
    const int tx = tid & 15, ty = tid >> 4;

    for (int i = tid; i < 1280; i += 256) {
        int j = i >> 7, n = i & 127;
        W2t[j][n] = g_W2[hd*1280 + n*10 + j];
    }
    if (tid < 10) b2s[tid] = g_b2[hd*10 + tid];

    float bias[8];
    #pragma unroll
    for (int n = 0; n < 8; n++) bias[n] = g_b1f[hd*128 + tx*8 + n];

    const float* A  = feats + (long long)row0 * 128;
    const float* Bp = g_W1f + hd * 16384;
    const int arow = tid >> 1, ac = (tid & 1) * 4;
    const int bk = tid >> 5, bd = (tid & 31) * 4;

    unsigned long long acc[8][4];
    #pragma unroll
    for (int m = 0; m < 8; m++)
        #pragma unroll
        for (int p = 0; p < 4; p++) acc[m][p] = 0ull;

    float4 a4 = *(const float4*)(A + arow*128 + ac);
    float4 b4 = *(const float4*)(Bp + bk*128 + bd);
    As[0][ac+0][arow] = a4.x; As[0][ac+1][arow] = a4.y;
    As[0][ac+2][arow] = a4.z; As[0][ac+3][arow] = a4.w;
    *(float4*)&Bs[0][bk][bd] = b4;
    __syncthreads();

    int buf = 0;
    for (int s = 0; s < 16; ++s) {
        float4 na, nb;
        if (s < 15) {
            na = *(const float4*)(A + arow*128 + (s+1)*8 + ac);
            nb = *(const float4*)(Bp + ((s+1)*8 + bk)*128 + bd);
        }
        #pragma unroll
        for (int kk = 0; kk < 8; kk++) {
            float4 af0 = *(const float4*)&As[buf][kk][ty*8];
            float4 af1 = *(const float4*)&As[buf][kk][ty*8 + 4];
            ulonglong2 b01 = *(const ulonglong2*)&Bs[buf][kk][tx*8];
            ulonglong2 b23 = *(const ulonglong2*)&Bs[buf][kk][tx*8 + 4];
            float am[8] = {af0.x, af0.y, af0.z, af0.w, af1.x, af1.y, af1.z, af1.w};
            #pragma unroll
            for (int m = 0; m < 8; m++) {
                unsigned long long pa = pack2(am[m]);
                ffma2(acc[m][0], pa, b01.x);
                ffma2(acc[m][1], pa, b01.y);
                ffma2(acc[m][2], pa, b23.x);
                ffma2(acc[m][3], pa, b23.y);
            }
        }
        if (s < 15) {
            buf ^= 1;
            As[buf][ac+0][arow] = na.x; As[buf][ac+1][arow] = na.y;
            As[buf][ac+2][arow] = na.z; As[buf][ac+3][arow] = na.w;
            *(float4*)&Bs[buf][bk][bd] = nb;
            __syncthreads();
        }
    }

    float h8[8][8];
    #pragma unroll
    for (int m = 0; m < 8; m++)
        #pragma unroll
        for (int p = 0; p < 4; p++) {
            float2 v = unpack2(acc[m][p]);
            h8[m][2*p] = v.x; h8[m][2*p+1] = v.y;
        }

    // epilogue: relu(h)+bias through strips of 32 columns, second GEMM to <=10 outputs
    const int r  = tid & 127;
    const int j0 = tid >> 7;
    float oacc[5] = {0.f, 0.f, 0.f, 0.f, 0.f};

    for (int sp = 0; sp < 4; ++sp) {
        __syncthreads();
        if ((tx >> 2) == sp) {
            int nb2 = (tx & 3) * 8;
            #pragma unroll
            for (int m = 0; m < 8; m++)
                #pragma unroll
                for (int n = 0; n < 8; n++)
                    Hs[ty*8 + m][nb2 + n] = fmaxf(h8[m][n] + bias[n], 0.f);
        }
        __syncthreads();
        float hr[32];
        #pragma unroll
        for (int nn = 0; nn < 32; nn++) hr[nn] = Hs[r][nn];
        #pragma unroll
        for (int jj = 0; jj < 5; jj++) {
            int jv = j0 + 2*jj;
            float a = 0.f;
            #pragma unroll
            for (int q = 0; q < 8; q++) {
                float4 w = *(const float4*)&W2t[jv][sp*32 + q*4];
                a += hr[q*4]*w.x + hr[q*4+1]*w.y + hr[q*4+2]*w.z + hr[q*4+3]*w.w;
            }
            oacc[jj] += a;
        }
    }

    const int oc_tab[6]  = {10,2,1,3,2,2};
    const int off_tab[6] = {0,0,2,3,6,8};
    int row = row0 + r;
    #pragma unroll
    for (int jj = 0; jj < 5; jj++) {
        int jv = j0 + 2*jj;
        float v = oacc[jj] + b2s[jv];
        if (hd == 0)
            g_hm[row*10 + jv] = 1.f / (1.f + expf(-v));
        else if (jv < oc_tab[hd])
            g_outs[row*10 + off_tab[hd] + jv] = v;
    }
}

// ---------------- top-k machinery (bitonic on composite keys) ----------------
__device__ __forceinline__ unsigned fkey(float f) {
    unsigned u = __float_as_uint(f);
    return (u & 0x80000000u) ? ~u : (u | 0x80000000u);
}
__device__ __forceinline__ float unfkey(unsigned u) {
    return (u & 0x80000000u) ? __uint_as_float(u ^ 0x80000000u) : __uint_as_float(~u);
}

template<int NT>
__device__ void bitonic(unsigned long long* s, int n) {
    int tid = threadIdx.x;
    for (int k = 2; k <= n; k <<= 1)
        for (int j = k >> 1; j > 0; j >>= 1) {
            __syncthreads();
            for (int i = tid; i < n; i += NT) {
                int ixj = i ^ j;
                if (ixj > i) {
                    unsigned long long a = s[i], b = s[ixj];
                    bool up = ((i & k) == 0);
                    if ((a > b) == up) { s[i] = b; s[ixj] = a; }
                }
            }
        }
    __syncthreads();
}

// stage 1: per (b, cls, chunk-of-4096): keep top 500 candidates
__global__ void topk_stage1() {
    __shared__ unsigned long long sk[4096];
    int chunk = blockIdx.x, cls = blockIdx.y, b = blockIdx.z;
    int tid = threadIdx.x;
    for (int i = tid; i < 4096; i += 512) {
        int v = chunk*4096 + i;
        float sc = g_hm[(b*NVOX + v)*10 + cls];
        sk[i] = (((unsigned long long)fkey(sc)) << 32) | (unsigned)(0xFFFFFFFFu - (unsigned)v);
    }
    bitonic<512>(sk, 4096);
    for (int rr = tid; rr < 500; rr += 512)
        g_cand[(((b*NCLASS + cls)*8) + chunk)*500 + rr] = sk[4095 - rr];
}

// stage 2: per (b, cls): top 500 of 4000 candidates, sorted desc (stable by voxel idx)
__global__ void topk_stage2() {
    __shared__ unsigned long long sk[4096];
    int cls = blockIdx.x, b = blockIdx.y;
    int tid = threadIdx.x;
    for (int i = tid; i < 4096; i += 512)
        sk[i] = (i < 4000) ? g_cand[(b*NCLASS + cls)*4000 + i] : 0ull;
    bitonic<512>(sk, 4096);
    for (int rr = tid; rr < 500; rr += 512) {
        unsigned long long kk = sk[4095 - rr];
        g_pc_score[(b*NCLASS + cls)*500 + rr] = unfkey((unsigned)(kk >> 32));
        g_pc_vox[(b*NCLASS + cls)*500 + rr]   = (int)(0xFFFFFFFFu - (unsigned)(kk & 0xFFFFFFFFull));
    }
}

// stage 3: per b: global top 500 of NCLASS*500 (stable by flat position)
__global__ void topk_stage3() {
    extern __shared__ unsigned long long sk[];
    int b = blockIdx.x;
    int tid = threadIdx.x;
    for (int i = tid; i < 8192; i += 1024) {
        unsigned long long kk = 0ull;
        if (i < NCLASS*500) {
            float sc = g_pc_score[b*NCLASS*500 + i];
            kk = (((unsigned long long)fkey(sc)) << 32) | (unsigned)(0xFFFFFFFFu - (unsigned)i);
        }
        sk[i] = kk;
    }
    bitonic<1024>(sk, 8192);
    for (int q = tid; q < 500; q += 1024) {
        unsigned long long kk = sk[8191 - q];
        unsigned p = 0xFFFFFFFFu - (unsigned)(kk & 0xFFFFFFFFull);
        g_top_score[b*500 + q] = unfkey((unsigned)(kk >> 32));
        g_top_cls[b*500 + q]   = (int)(p / 500);
        g_top_vox[b*500 + q]   = g_pc_vox[b*NCLASS*500 + p];
    }
}

// ---------------- final decode + output ----------------
__global__ void decode_kernel(const int* __restrict__ voxel_xy, float* __restrict__ out, int out_size) {
    int b = blockIdx.x;
    int q = threadIdx.x;
    if (q >= 500) return;
    int i = b*500 + q;
    float score = g_top_score[i];
    int cls = g_top_cls[i];
    int v = g_top_vox[i];
    int row = b*NVOX + v;
    const float* o = &g_outs[row*10];
    float cx = o[0], cy = o[1], cz = o[2];
    float dx = expf(o[3]), dy = expf(o[4]), dz = expf(o[5]);
    float ang = atan2f(o[7], o[6]);
    float vx = o[8], vy = o[9];
    float x = (float)voxel_xy[row*2 + 0];
    float y = (float)voxel_xy[row*2 + 1];
    float xs = (x + cx) * 8.0f * 0.075f + (-54.0f);
    float ys = (y + cy) * 8.0f * 0.075f + (-54.0f);
    bool m = (xs >= -61.2f) && (ys >= -61.2f) && (cz >= -10.0f) &&
             (xs <=  61.2f) && (ys <=  61.2f) && (cz <=  10.0f) && (score > 0.1f);
    float mf = m ? 1.f : 0.f;
    float* bs = &out[i*10];
    bs[0] = xs*mf; bs[1] = ys*mf; bs[2] = cz*mf;
    bs[3] = dx*mf; bs[4] = dy*mf; bs[5] = dz*mf;
    bs[6] = ang*mf; bs[7] = vx*mf; bs[8] = vy*mf; bs[9] = score*mf;
    if (out_size >= 22000) out[20000 + i] = m ? (float)(cls + 1) : 0.f;
    if (out_size >= 24000) out[22000 + i] = (float)(v + b*NVOX);
    if (out_size >= 26000) out[24000 + i] = mf;
}

// ---------------- launch ----------------
extern "C" void kernel_launch(void* const* d_in, const int* in_sizes, int n_in,
                              void* d_out, int out_size) {
    const float* feats    = (const float*)d_in[0];
    const int*   voxel_xy = (const int*)d_in[1];
    Ptrs P;
    P.W1 = (const float*)d_in[2];
    P.b1 = (const float*)d_in[3];
    P.ga = (const float*)d_in[4];
    P.be = (const float*)d_in[5];
    P.mu = (const float*)d_in[6];
    P.va = (const float*)d_in[7];
    for (int h = 0; h < 6; h++) {
        P.W2[h] = (const float*)d_in[8 + 2*h];
        P.b2[h] = (const float*)d_in[9 + 2*h];
    }

    fold_kernel<<<(6*128*128 + 255)/256, 256>>>(P);
    head_gemm<<<dim3(1024, 6), 256>>>(feats);
    topk_stage1<<<dim3(8, NCLASS, BATCH), 512>>>();
    topk_stage2<<<dim3(NCLASS, BATCH), 512>>>();
    cudaFuncSetAttribute(topk_stage3, cudaFuncAttributeMaxDynamicSharedMemorySize, 65536);
    topk_stage3<<<BATCH, 1024, 65536>>>();
    decode_kernel<<<BATCH, 512>>>(voxel_xy, (float*)d_out, out_size);
}

// round 10
// speedup vs baseline: 1.3689x; 1.3689x over previous
#include <cuda_runtime.h>
#include <math.h>

#define NVOX   32768
#define BATCH  4
#define NROWS  (BATCH*NVOX)
#define NCLASS 10
#define TOPK   500

// ---------------- static device scratch (no allocations allowed) ----------------
__device__ float g_W1f[6*128*128];   // BN-folded first-layer weights
__device__ float g_b1f[6*128];       // BN-folded bias
__device__ float g_W2[6*128*10];     // padded second-layer weights [head][n][j]
__device__ float g_b2[6*10];
__device__ float g_hm_t[NCLASS*NROWS]; // transposed sigmoid heatmap [cls][row]
__device__ float g_outs[NROWS*10];   // center(2) center_z(1) dim(3) rot(2) vel(2)
__device__ float g_pc_score[BATCH*NCLASS*500];
__device__ int   g_pc_vox[BATCH*NCLASS*500];

__constant__ int c_oc[6] = {10,2,1,3,2,2};

struct Ptrs {
    const float* W1; const float* b1;
    const float* ga; const float* be; const float* mu; const float* va;
    const float* W2[6]; const float* b2[6];
};

// ---------------- BN fold + weight packing ----------------
__global__ void fold_kernel(Ptrs P) {
    int idx = blockIdx.x * blockDim.x + threadIdx.x;
    if (idx < 6*128*128) {
        int hd = idx >> 14;
        int rem = idx & 16383;
        int c = rem >> 7;
        int d = rem & 127;
        float inv = P.ga[hd*128+d] / sqrtf(P.va[hd*128+d] + 1e-5f);
        g_W1f[idx] = P.W1[idx] * inv;
        if (c == 0)
            g_b1f[hd*128+d] = (P.b1[hd*128+d] - P.mu[hd*128+d]) * inv + P.be[hd*128+d];
    }
    if (idx < 6*1280) {
        int hd = idx / 1280, t = idx % 1280, n = t / 10, j = t % 10;
        int oc = c_oc[hd];
        g_W2[idx] = (j < oc) ? P.W2[hd][n*oc + j] : 0.f;
    }
    if (idx < 60) {
        int hd = idx / 10, j = idx % 10;
        g_b2[idx] = (j < c_oc[hd]) ? P.b2[hd][j] : 0.f;
    }
}

// ---------------- packed f32x2 helpers ----------------
__device__ __forceinline__ void ffma2(unsigned long long &d, unsigned long long a, unsigned long long b) {
    asm("fma.rn.f32x2 %0, %1, %2, %0;" : "+l"(d) : "l"(a), "l"(b));
}
__device__ __forceinline__ unsigned long long pack2(float x) {
    unsigned long long r; unsigned u = __float_as_uint(x);
    asm("mov.b64 %0, {%1, %1};" : "=l"(r) : "r"(u));
    return r;
}
__device__ __forceinline__ float2 unpack2(unsigned long long v) {
    unsigned lo, hi;
    asm("mov.b64 {%0, %1}, %2;" : "=r"(lo), "=r"(hi) : "l"(v));
    return make_float2(__uint_as_float(lo), __uint_as_float(hi));
}

// 16B-chunk XOR swizzle (bijective, conflict-free for our store/load patterns):
// row = 32 chunks of 4 floats; phys_chunk = chunk ^ ((chunk>>3)&3)
__device__ __forceinline__ int swz(int chunk) { return chunk ^ ((chunk >> 3) & 3); }

// ---------------- fused head GEMM: h = relu(feats@W1f + b1f); out = h@W2 + b2 ----------------
// grid (1024, 6): x = 128-row tile, y = head. 256 threads, 8x8 microtile, BK=8 double-buffered.
__global__ void __launch_bounds__(256, 2) head_gemm(const float* __restrict__ feats) {
    __shared__ __align__(16) float As[2][8][128];
    __shared__ __align__(16) float Bs[2][8][128];
    __shared__ __align__(16) float Hs[128][33];
    __shared__ __align__(16) float W2t[10][128];
    __shared__ float b2s[10];

    const int tid = threadIdx.x;
    const int hd  = blockIdx.y;
    const int row0 = blockIdx.x * 128;
    const int tx = tid & 15, ty = tid >> 4;

    for (int i = tid; i < 1280; i += 256) {
        int j = i >> 7, n = i & 127;
        W2t[j][n] = g_W2[hd*1280 + n*10 + j];
    }
    if (tid < 10) b2s[tid] = g_b2[hd*10 + tid];

    float bias[8];
    #pragma unroll
    for (int n = 0; n < 8; n++) bias[n] = g_b1f[hd*128 + tx*8 + n];

    const float* A  = feats + (long long)row0 * 128;
    const float* Bp = g_W1f + hd * 16384;
    const int arow = tid >> 1, ac = (tid & 1) * 4;
    const int bk = tid >> 5, bd = (tid & 31) * 4;
    const int bphys = swz(tid & 31) * 4;          // swizzled store col (floats)
    const int p0 = swz(2 * tx) * 4;               // swizzled load col for chunk 2tx
    const int p1 = (swz(2 * tx) ^ 1) * 4;         // chunk 2tx+1 (same 128B line -> ^1)

    unsigned long long acc[8][4];
    #pragma unroll
    for (int m = 0; m < 8; m++)
        #pragma unroll
        for (int p = 0; p < 4; p++) acc[m][p] = 0ull;

    float4 a4 = *(const float4*)(A + arow*128 + ac);
    float4 b4 = *(const float4*)(Bp + bk*128 + bd);
    As[0][ac+0][arow] = a4.x; As[0][ac+1][arow] = a4.y;
    As[0][ac+2][arow] = a4.z; As[0][ac+3][arow] = a4.w;
    *(float4*)&Bs[0][bk][bphys] = b4;
    __syncthreads();

    int buf = 0;
    for (int s = 0; s < 16; ++s) {
        float4 na, nb;
        if (s < 15) {
            na = *(const float4*)(A + arow*128 + (s+1)*8 + ac);
            nb = *(const float4*)(Bp + ((s+1)*8 + bk)*128 + bd);
        }
        #pragma unroll
        for (int kk = 0; kk < 8; kk++) {
            float4 af0 = *(const float4*)&As[buf][kk][ty*8];
            float4 af1 = *(const float4*)&As[buf][kk][ty*8 + 4];
            ulonglong2 b01 = *(const ulonglong2*)&Bs[buf][kk][p0];
            ulonglong2 b23 = *(const ulonglong2*)&Bs[buf][kk][p1];
            float am[8] = {af0.x, af0.y, af0.z, af0.w, af1.x, af1.y, af1.z, af1.w};
            #pragma unroll
            for (int m = 0; m < 8; m++) {
                unsigned long long pa = pack2(am[m]);
                ffma2(acc[m][0], pa, b01.x);
                ffma2(acc[m][1], pa, b01.y);
                ffma2(acc[m][2], pa, b23.x);
                ffma2(acc[m][3], pa, b23.y);
            }
        }
        if (s < 15) {
            buf ^= 1;
            As[buf][ac+0][arow] = na.x; As[buf][ac+1][arow] = na.y;
            As[buf][ac+2][arow] = na.z; As[buf][ac+3][arow] = na.w;
            *(float4*)&Bs[buf][bk][bphys] = nb;
            __syncthreads();
        }
    }

    float h8[8][8];
    #pragma unroll
    for (int m = 0; m < 8; m++)
        #pragma unroll
        for (int p = 0; p < 4; p++) {
            float2 v = unpack2(acc[m][p]);
            h8[m][2*p] = v.x; h8[m][2*p+1] = v.y;
        }

    // epilogue: relu(h)+bias through strips of 32 columns, second GEMM to <=10 outputs
    const int r  = tid & 127;
    const int j0 = tid >> 7;
    float oacc[5] = {0.f, 0.f, 0.f, 0.f, 0.f};

    for (int sp = 0; sp < 4; ++sp) {
        __syncthreads();
        if ((tx >> 2) == sp) {
            int nb2 = (tx & 3) * 8;
            #pragma unroll
            for (int m = 0; m < 8; m++)
                #pragma unroll
                for (int n = 0; n < 8; n++)
                    Hs[ty*8 + m][nb2 + n] = fmaxf(h8[m][n] + bias[n], 0.f);
        }
        __syncthreads();
        float hr[32];
        #pragma unroll
        for (int nn = 0; nn < 32; nn++) hr[nn] = Hs[r][nn];
        #pragma unroll
        for (int jj = 0; jj < 5; jj++) {
            int jv = j0 + 2*jj;
            float a = 0.f;
            #pragma unroll
            for (int q = 0; q < 8; q++) {
                float4 w = *(const float4*)&W2t[jv][sp*32 + q*4];
                a += hr[q*4]*w.x + hr[q*4+1]*w.y + hr[q*4+2]*w.z + hr[q*4+3]*w.w;
            }
            oacc[jj] += a;
        }
    }

    const int oc_tab[6]  = {10,2,1,3,2,2};
    const int off_tab[6] = {0,0,2,3,6,8};
    int row = row0 + r;
    #pragma unroll
    for (int jj = 0; jj < 5; jj++) {
        int jv = j0 + 2*jj;
        float v = oacc[jj] + b2s[jv];
        if (hd == 0)
            g_hm_t[jv*NROWS + row] = 1.f / (1.f + expf(-v));   // transposed: coalesced write
        else if (jv < oc_tab[hd])
            g_outs[row*10 + off_tab[hd] + jv] = v;
    }
}

// ---------------- top-k machinery ----------------
__device__ __forceinline__ unsigned fkey(float f) {
    unsigned u = __float_as_uint(f);
    return (u & 0x80000000u) ? ~u : (u | 0x80000000u);
}
__device__ __forceinline__ float unfkey(unsigned u) {
    return (u & 0x80000000u) ? __uint_as_float(u ^ 0x80000000u) : __uint_as_float(~u);
}

template<int NT>
__device__ void bitonic(unsigned long long* s, int n) {
    int tid = threadIdx.x;
    for (int k = 2; k <= n; k <<= 1)
        for (int j = k >> 1; j > 0; j >>= 1) {
            __syncthreads();
            for (int i = tid; i < n; i += NT) {
                int ixj = i ^ j;
                if (ixj > i) {
                    unsigned long long a = s[i], b = s[ixj];
                    bool up = ((i & k) == 0);
                    if ((a > b) == up) { s[i] = b; s[ixj] = a; }
                }
            }
        }
    __syncthreads();
}

// find bucket T (descending) such that cnt(> T) < need <= cnt(>= T); 512 threads, 2048 buckets
__device__ void find_threshold(unsigned* hist, int need, int* outT, int* outCnt, unsigned* scanbuf) {
    int tid = threadIdx.x;
    int hi = 2047 - 4*tid;
    unsigned s = hist[hi] + hist[hi-1] + hist[hi-2] + hist[hi-3];
    scanbuf[tid] = s;
    __syncthreads();
    for (int off = 1; off < 512; off <<= 1) {
        unsigned v = (tid >= off) ? scanbuf[tid - off] : 0u;
        __syncthreads();
        scanbuf[tid] += v;
        __syncthreads();
    }
    unsigned cum = (tid == 0) ? 0u : scanbuf[tid - 1];
    #pragma unroll
    for (int j = 0; j < 4; j++) {
        unsigned h = hist[hi - j];
        if ((int)cum < need && (int)(cum + h) >= need) { *outT = hi - j; *outCnt = (int)cum; }
        cum += h;
    }
}

// exact per-(b,cls) top-500 via two-level histogram select + small sort
__global__ void __launch_bounds__(512) topk_perclass() {
    __shared__ unsigned hist[2048];
    __shared__ unsigned scanbuf[512];
    __shared__ unsigned long long buf[1024];
    __shared__ int s_T1, s_c1, s_T2, s_c2, s_n;
    const int cls = blockIdx.x, b = blockIdx.y, tid = threadIdx.x;
    const float* __restrict__ base = g_hm_t + cls*NROWS + b*NVOX;

    for (int i = tid; i < 2048; i += 512) hist[i] = 0u;
    __syncthreads();
    for (int v = tid; v < NVOX; v += 512)
        atomicAdd(&hist[fkey(base[v]) >> 21], 1u);
    __syncthreads();
    find_threshold(hist, 500, &s_T1, &s_c1, scanbuf);
    __syncthreads();
    const int T1 = s_T1;
    const int need2 = 500 - s_c1;

    for (int i = tid; i < 2048; i += 512) hist[i] = 0u;
    __syncthreads();
    for (int v = tid; v < NVOX; v += 512) {
        unsigned k = fkey(base[v]);
        if ((int)(k >> 21) == T1) atomicAdd(&hist[(k >> 10) & 0x7FFu], 1u);
    }
    __syncthreads();
    find_threshold(hist, need2, &s_T2, &s_c2, scanbuf);
    if (tid == 0) s_n = 0;
    for (int i = tid; i < 1024; i += 512) buf[i] = 0ull;
    __syncthreads();
    const int T2 = s_T2;

    for (int v = tid; v < NVOX; v += 512) {
        unsigned k = fkey(base[v]);
        int k1 = (int)(k >> 21), k2 = (int)((k >> 10) & 0x7FFu);
        if (k1 > T1 || (k1 == T1 && k2 >= T2)) {
            int pos = atomicAdd(&s_n, 1);
            if (pos < 1024)
                buf[pos] = (((unsigned long long)k) << 32) | (unsigned)(0xFFFFFFFFu - (unsigned)v);
        }
    }
    __syncthreads();
    bitonic<512>(buf, 1024);   // ascending; top at the end
    for (int r = tid; r < 500; r += 512) {
        unsigned long long kk = buf[1023 - r];
        g_pc_score[(b*NCLASS + cls)*500 + r] = unfkey((unsigned)(kk >> 32));
        g_pc_vox[(b*NCLASS + cls)*500 + r]   = (int)(0xFFFFFFFFu - (unsigned)(kk & 0xFFFFFFFFull));
    }
}

// global top-500 of 5000 per batch (tiebreak: smaller flat p first) + fused decode
__global__ void __launch_bounds__(512) topk_global_decode(const int* __restrict__ voxel_xy,
                                                          float* __restrict__ out, int out_size) {
    __shared__ unsigned hist[2048];
    __shared__ unsigned scanbuf[512];
    __shared__ unsigned long long buf[1024];
    __shared__ int s_T1, s_c1, s_T2, s_c2, s_n;
    const int b = blockIdx.x, tid = threadIdx.x;
    const float* __restrict__ base = g_pc_score + b*NCLASS*500;
    const int N2 = NCLASS*500;

    for (int i = tid; i < 2048; i += 512) hist[i] = 0u;
    __syncthreads();
    for (int p = tid; p < N2; p += 512)
        atomicAdd(&hist[fkey(base[p]) >> 21], 1u);
    __syncthreads();
    find_threshold(hist, 500, &s_T1, &s_c1, scanbuf);
    __syncthreads();
    const int T1 = s_T1;
    const int need2 = 500 - s_c1;

    for (int i = tid; i < 2048; i += 512) hist[i] = 0u;
    __syncthreads();
    for (int p = tid; p < N2; p += 512) {
        unsigned k = fkey(base[p]);
        if ((int)(k >> 21) == T1) atomicAdd(&hist[(k >> 10) & 0x7FFu], 1u);
    }
    __syncthreads();
    find_threshold(hist, need2, &s_T2, &s_c2, scanbuf);
    if (tid == 0) s_n = 0;
    for (int i = tid; i < 1024; i += 512) buf[i] = 0ull;
    __syncthreads();
    const int T2 = s_T2;

    for (int p = tid; p < N2; p += 512) {
        unsigned k = fkey(base[p]);
        int k1 = (int)(k >> 21), k2 = (int)((k >> 10) & 0x7FFu);
        if (k1 > T1 || (k1 == T1 && k2 >= T2)) {
            int pos = atomicAdd(&s_n, 1);
            if (pos < 1024)
                buf[pos] = (((unsigned long long)k) << 32) | (unsigned)(0xFFFFFFFFu - (unsigned)p);
        }
    }
    __syncthreads();
    bitonic<512>(buf, 1024);

    // fused decode
    for (int q = tid; q < 500; q += 512) {
        unsigned long long kk = buf[1023 - q];
        float score = unfkey((unsigned)(kk >> 32));
        unsigned p = 0xFFFFFFFFu - (unsigned)(kk & 0xFFFFFFFFull);
        int cls = (int)(p / 500);
        int v = g_pc_vox[b*NCLASS*500 + p];
        int row = b*NVOX + v;
        const float* o = &g_outs[row*10];
        float cx = o[0], cy = o[1], cz = o[2];
        float dx = expf(o[3]), dy = expf(o[4]), dz = expf(o[5]);
        float ang = atan2f(o[7], o[6]);
        float vx = o[8], vy = o[9];
        float x = (float)voxel_xy[row*2 + 0];
        float y = (float)voxel_xy[row*2 + 1];
        float xs = (x + cx) * 8.0f * 0.075f + (-54.0f);
        float ys = (y + cy) * 8.0f * 0.075f + (-54.0f);
        bool m = (xs >= -61.2f) && (ys >= -61.2f) && (cz >= -10.0f) &&
                 (xs <=  61.2f) && (ys <=  61.2f) && (cz <=  10.0f) && (score > 0.1f);
        float mf = m ? 1.f : 0.f;
        int i = b*500 + q;
        float* bs = &out[i*10];
        bs[0] = xs*mf; bs[1] = ys*mf; bs[2] = cz*mf;
        bs[3] = dx*mf; bs[4] = dy*mf; bs[5] = dz*mf;
        bs[6] = ang*mf; bs[7] = vx*mf; bs[8] = vy*mf; bs[9] = score*mf;
        if (out_size >= 22000) out[20000 + i] = m ? (float)(cls + 1) : 0.f;
        if (out_size >= 24000) out[22000 + i] = (float)(v + b*NVOX);
        if (out_size >= 26000) out[24000 + i] = mf;
    }
}

// ---------------- launch ----------------
extern "C" void kernel_launch(void* const* d_in, const int* in_sizes, int n_in,
                              void* d_out, int out_size) {
    const float* feats    = (const float*)d_in[0];
    const int*   voxel_xy = (const int*)d_in[1];
    Ptrs P;
    P.W1 = (const float*)d_in[2];
    P.b1 = (const float*)d_in[3];
    P.ga = (const float*)d_in[4];
    P.be = (const float*)d_in[5];
    P.mu = (const float*)d_in[6];
    P.va = (const float*)d_in[7];
    for (int h = 0; h < 6; h++) {
        P.W2[h] = (const float*)d_in[8 + 2*h];
        P.b2[h] = (const float*)d_in[9 + 2*h];
    }

    fold_kernel<<<(6*128*128 + 255)/256, 256>>>(P);
    head_gemm<<<dim3(1024, 6), 256>>>(feats);
    topk_perclass<<<dim3(NCLASS, BATCH), 512>>>();
    topk_global_decode<<<BATCH, 512>>>(voxel_xy, (float*)d_out, out_size);
}